// round 1
// baseline (speedup 1.0000x reference)
#include <cuda_runtime.h>

#define NH   12
#define SLEN 4096
#define HD   64
#define DIM  768
#define GRD  64   // h = w = 64

// ---------------- scratch (static device allocations; no cudaMalloc) --------
__device__ float g_Q[NH * SLEN * HD];      // unscaled q, [head][s][c]
__device__ float g_K[NH * SLEN * HD];
__device__ float g_V[NH * SLEN * HD];
__device__ float g_relh[NH * SLEN * GRD];  // [head][qpos][kh]
__device__ float g_relw[NH * SLEN * GRD];  // [head][qpos][kw]
__device__ float g_ao[SLEN * DIM];         // attention output, [s][head*64+c]

// ---------------- GEMM  C[M,N] = X[M,K] @ W[N,K]^T + b ----------------------
// 64x64 tile, BK=16, 256 threads, 4x4 micro-tile.
// EPI==0: scatter into g_Q/g_K/g_V (qkv).  EPI==1: X := g_ao, write to out.
template <int EPI>
__global__ void gemm_nt(const float* __restrict__ Xin,
                        const float* __restrict__ W,
                        const float* __restrict__ bias,
                        float* __restrict__ out)
{
    const float* X = (EPI == 1) ? (const float*)g_ao : Xin;
    __shared__ float As[16][68];   // As[kk][i]
    __shared__ float Bs[16][68];   // Bs[kk][j]
    const int bm = blockIdx.y * 64;
    const int bn = blockIdx.x * 64;
    const int tid = threadIdx.x;
    const int tx = tid & 15, ty = tid >> 4;
    const int lr = tid >> 2, lk = (tid & 3) << 2;

    float acc[4][4] = {};
    for (int k0 = 0; k0 < DIM; k0 += 16) {
        float4 xa = *(const float4*)&X[(size_t)(bm + lr) * DIM + k0 + lk];
        As[lk + 0][lr] = xa.x; As[lk + 1][lr] = xa.y;
        As[lk + 2][lr] = xa.z; As[lk + 3][lr] = xa.w;
        float4 wb = *(const float4*)&W[(size_t)(bn + lr) * DIM + k0 + lk];
        Bs[lk + 0][lr] = wb.x; Bs[lk + 1][lr] = wb.y;
        Bs[lk + 2][lr] = wb.z; Bs[lk + 3][lr] = wb.w;
        __syncthreads();
#pragma unroll
        for (int kk = 0; kk < 16; kk++) {
            float4 a = *(const float4*)&As[kk][ty << 2];
            float4 b = *(const float4*)&Bs[kk][tx << 2];
            float av[4] = {a.x, a.y, a.z, a.w};
            float bv[4] = {b.x, b.y, b.z, b.w};
#pragma unroll
            for (int i = 0; i < 4; i++)
#pragma unroll
                for (int j = 0; j < 4; j++) acc[i][j] += av[i] * bv[j];
        }
        __syncthreads();
    }

    if (EPI == 0) {
        // j in [bn, bn+64): 'which' and 'head' are constant per block.
        const int jbase = bn + (tx << 2);
        const int which = bn / DIM;
        const int head  = (bn % DIM) / HD;
        float* dst = (which == 0) ? g_Q : (which == 1) ? g_K : g_V;
#pragma unroll
        for (int i = 0; i < 4; i++) {
            const int s = bm + (ty << 2) + i;
#pragma unroll
            for (int j = 0; j < 4; j++) {
                const int jj = jbase + j;
                const int c  = jj & 63;
                dst[((size_t)head * SLEN + s) * HD + c] = acc[i][j] + bias[jj];
            }
        }
    } else {
#pragma unroll
        for (int i = 0; i < 4; i++) {
            const int s = bm + (ty << 2) + i;
#pragma unroll
            for (int j = 0; j < 4; j++) {
                const int jj = bn + (tx << 2) + j;
                out[(size_t)s * DIM + jj] = acc[i][j] + bias[jj];
            }
        }
    }
}

// ---------------- rel-pos bias ----------------------------------------------
// isW==0: rel_h[head][qh*64+qw][kh] = sum_c Q[.][c] * rph[(qh-kh+63)][c]
// isW==1: rel_w[head][qh*64+qw][kw] = sum_c Q[.][c] * rpw[(qw-kw+63)][c]
#define REL_SM_FLOATS (64 * 68 + 127 * 65)
__global__ void rel_kernel(const float* __restrict__ relpos, int isW)
{
    extern __shared__ float sm[];
    float* Qs = sm;               // [64][68]  Qs[c][qw]
    float* R  = sm + 64 * 68;
    const int qh = blockIdx.x, head = blockIdx.y;
    const int tid = threadIdx.x;
    const int tx = tid & 15, ty = tid >> 4;

    const float* Qg = &g_Q[((size_t)head * SLEN + qh * GRD) * HD];
    for (int t = tid; t < 4096; t += 256) {
        int c = t & 63, qw = t >> 6;
        Qs[c * 68 + qw] = Qg[(size_t)qw * HD + c];
    }

    if (!isW) {
        // R[c][kh] = relpos[(qh-kh+63)*64 + c], pad 68
        for (int t = tid; t < 4096; t += 256) {
            int c = t & 63, kh = t >> 6;
            R[c * 68 + kh] = relpos[(qh - kh + 63) * 64 + c];
        }
        __syncthreads();
        float acc[4][4] = {};
#pragma unroll 4
        for (int c = 0; c < 64; c++) {
            float4 a = *(const float4*)&Qs[c * 68 + (ty << 2)];
            float4 b = *(const float4*)&R[c * 68 + (tx << 2)];
            float av[4] = {a.x, a.y, a.z, a.w};
            float bv[4] = {b.x, b.y, b.z, b.w};
#pragma unroll
            for (int i = 0; i < 4; i++)
#pragma unroll
                for (int j = 0; j < 4; j++) acc[i][j] += av[i] * bv[j];
        }
#pragma unroll
        for (int i = 0; i < 4; i++)
#pragma unroll
            for (int j = 0; j < 4; j++) {
                int qw = (ty << 2) + i, kh = (tx << 2) + j;
                g_relh[((size_t)head * SLEN + qh * 64 + qw) * 64 + kh] = acc[i][j];
            }
    } else {
        // R[row][c], row = qw-kw+63 in [0,126], pad 65
        for (int t = tid; t < 127 * 64; t += 256) {
            int c = t & 63, rr = t >> 6;
            R[rr * 65 + c] = relpos[rr * 64 + c];
        }
        __syncthreads();
        float acc[4][4] = {};
        const int qwb = ty << 2, kwb = tx << 2;
        for (int c = 0; c < 64; c++) {
            float4 a = *(const float4*)&Qs[c * 68 + qwb];
            float av[4] = {a.x, a.y, a.z, a.w};
#pragma unroll
            for (int i = 0; i < 4; i++)
#pragma unroll
                for (int j = 0; j < 4; j++)
                    acc[i][j] += av[i] * R[(qwb + i - kwb - j + 63) * 65 + c];
        }
#pragma unroll
        for (int i = 0; i < 4; i++)
#pragma unroll
            for (int j = 0; j < 4; j++) {
                int qw = qwb + i, kw = kwb + j;
                g_relw[((size_t)head * SLEN + qh * 64 + qw) * 64 + kw] = acc[i][j];
            }
    }
}

// ---------------- flash attention -------------------------------------------
// block = (q-tile of 64, head). Key tile kt covers key positions kt*64..+63,
// i.e. exactly key-grid row kh = kt  ->  rel_h contributes one scalar per query
// per tile, rel_w a block-resident [64][64] tile.
#define OFF_QS 0                    // [64][68]  Qs[c][qi]
#define OFF_KS (OFF_QS + 64 * 68)   // [64][68]  Ks[c][kj]
#define OFF_VS (OFF_KS + 64 * 68)   // [64][64]  Vs[kj][c]
#define OFF_SS (OFF_VS + 64 * 64)   // [64][68]  scores / probs
#define OFF_RW (OFF_SS + 64 * 68)   // [64][64]
#define OFF_RH (OFF_RW + 64 * 64)   // [64]
#define OFF_M  (OFF_RH + 64)
#define OFF_L  (OFF_M + 64)
#define OFF_A  (OFF_L + 64)
#define ATTN_SM_FLOATS (OFF_A + 64)

__global__ void attn_kernel()
{
    extern __shared__ float sm[];
    float* Qs = sm + OFF_QS;
    float* Ks = sm + OFF_KS;
    float* Vs = sm + OFF_VS;
    float* Ss = sm + OFF_SS;
    float* Rw = sm + OFF_RW;
    float* rh = sm + OFF_RH;
    float* ms = sm + OFF_M;
    float* ls = sm + OFF_L;
    float* al = sm + OFF_A;

    const int qt = blockIdx.x, head = blockIdx.y;
    const int q0 = qt * 64;
    const int tid = threadIdx.x;
    const int tx = tid & 15, ty = tid >> 4;
    const float scale = 0.125f;   // 64^-0.5

    const float* Qg = &g_Q[((size_t)head * SLEN + q0) * HD];
    for (int t = tid; t < 4096; t += 256) {
        int c = t & 63, qi = t >> 6;
        Qs[c * 68 + qi] = Qg[(size_t)qi * HD + c];
        Rw[t] = g_relw[((size_t)head * SLEN + q0 + qi) * 64 + c];  // qi,kw=c
    }
    if (tid < 64) { ms[tid] = -1e30f; ls[tid] = 0.0f; }

    float o[4][4] = {};
    __syncthreads();

    for (int kt = 0; kt < 64; kt++) {
        const float* Kg = &g_K[((size_t)head * SLEN + kt * 64) * HD];
        const float* Vg = &g_V[((size_t)head * SLEN + kt * 64) * HD];
        for (int t = tid; t < 4096; t += 256) {
            int c = t & 63, kj = t >> 6;
            Ks[c * 68 + kj] = Kg[(size_t)kj * HD + c];
            Vs[kj * 64 + c] = Vg[(size_t)kj * HD + c];
        }
        if (tid < 64)
            rh[tid] = g_relh[((size_t)head * SLEN + q0 + tid) * 64 + kt];
        __syncthreads();

        // ---- scores: S = scale * Q K^T + rel ----
        float acc[4][4] = {};
#pragma unroll 4
        for (int c = 0; c < 64; c++) {
            float4 a = *(const float4*)&Qs[c * 68 + (ty << 2)];
            float4 b = *(const float4*)&Ks[c * 68 + (tx << 2)];
            float av[4] = {a.x, a.y, a.z, a.w};
            float bv[4] = {b.x, b.y, b.z, b.w};
#pragma unroll
            for (int i = 0; i < 4; i++)
#pragma unroll
                for (int j = 0; j < 4; j++) acc[i][j] += av[i] * bv[j];
        }
#pragma unroll
        for (int i = 0; i < 4; i++) {
            const int qi = (ty << 2) + i;
            const float rhv = rh[qi];
            float4 rw4 = *(const float4*)&Rw[qi * 64 + (tx << 2)];
            float rw[4] = {rw4.x, rw4.y, rw4.z, rw4.w};
#pragma unroll
            for (int j = 0; j < 4; j++)
                Ss[qi * 68 + (tx << 2) + j] = acc[i][j] * scale + rhv + rw[j];
        }
        __syncthreads();

        // ---- online softmax (one thread per query row) ----
        if (tid < 64) {
            const int r = tid;
            float mt = -1e30f;
            for (int j = 0; j < 64; j++) mt = fmaxf(mt, Ss[r * 68 + j]);
            const float mo = ms[r];
            const float mn = fmaxf(mo, mt);
            float sum = 0.0f;
            for (int j = 0; j < 64; j++) {
                float p = __expf(Ss[r * 68 + j] - mn);
                Ss[r * 68 + j] = p;
                sum += p;
            }
            const float a = __expf(mo - mn);
            al[r] = a;
            ls[r] = ls[r] * a + sum;
            ms[r] = mn;
        }
        __syncthreads();

        // ---- rescale + P @ V ----
        float av4[4];
#pragma unroll
        for (int i = 0; i < 4; i++) av4[i] = al[(ty << 2) + i];
#pragma unroll
        for (int i = 0; i < 4; i++)
#pragma unroll
            for (int j = 0; j < 4; j++) o[i][j] *= av4[i];

        for (int kb = 0; kb < 64; kb += 4) {
            float pr[4][4];
#pragma unroll
            for (int i = 0; i < 4; i++) {
                float4 pa = *(const float4*)&Ss[((ty << 2) + i) * 68 + kb];
                pr[i][0] = pa.x; pr[i][1] = pa.y; pr[i][2] = pa.z; pr[i][3] = pa.w;
            }
#pragma unroll
            for (int kk = 0; kk < 4; kk++) {
                float4 v4 = *(const float4*)&Vs[(kb + kk) * 64 + (tx << 2)];
                float vv[4] = {v4.x, v4.y, v4.z, v4.w};
#pragma unroll
                for (int i = 0; i < 4; i++)
#pragma unroll
                    for (int j = 0; j < 4; j++) o[i][j] += pr[i][kk] * vv[j];
            }
        }
        __syncthreads();
    }

    // ---- normalize + write [s][head*64 + c] ----
    float linv[4];
#pragma unroll
    for (int i = 0; i < 4; i++) linv[i] = 1.0f / ls[(ty << 2) + i];
#pragma unroll
    for (int i = 0; i < 4; i++) {
        const int s = q0 + (ty << 2) + i;
#pragma unroll
        for (int j = 0; j < 4; j++)
            g_ao[(size_t)s * DIM + head * 64 + (tx << 2) + j] = o[i][j] * linv[i];
    }
}

// ---------------- launch ------------------------------------------------------
extern "C" void kernel_launch(void* const* d_in, const int* in_sizes, int n_in,
                              void* d_out, int out_size)
{
    const float* x      = (const float*)d_in[0];
    const float* qkv_w  = (const float*)d_in[1];
    const float* qkv_b  = (const float*)d_in[2];
    const float* proj_w = (const float*)d_in[3];
    const float* proj_b = (const float*)d_in[4];
    const float* rph    = (const float*)d_in[5];
    const float* rpw    = (const float*)d_in[6];
    float* out = (float*)d_out;

    const int rel_sm  = REL_SM_FLOATS * (int)sizeof(float);
    const int attn_sm = ATTN_SM_FLOATS * (int)sizeof(float);
    cudaFuncSetAttribute(rel_kernel,  cudaFuncAttributeMaxDynamicSharedMemorySize, rel_sm);
    cudaFuncSetAttribute(attn_kernel, cudaFuncAttributeMaxDynamicSharedMemorySize, attn_sm);

    // 1) qkv = x @ qkv_w^T + b -> Q,K,V scratch ([head][s][c], unscaled q)
    gemm_nt<0><<<dim3(3 * DIM / 64, SLEN / 64), 256>>>(x, qkv_w, qkv_b, nullptr);

    // 2) decomposed rel-pos bias tables
    rel_kernel<<<dim3(GRD, NH), 256, rel_sm>>>(rph, 0);
    rel_kernel<<<dim3(GRD, NH), 256, rel_sm>>>(rpw, 1);

    // 3) flash attention with fused rel bias
    attn_kernel<<<dim3(SLEN / 64, NH), 256, attn_sm>>>();

    // 4) out = attn_out @ proj_w^T + b
    gemm_nt<1><<<dim3(DIM / 64, SLEN / 64), 256>>>(nullptr, proj_w, proj_b, out);
}

// round 3
// speedup vs baseline: 2.0563x; 2.0563x over previous
#include <cuda_runtime.h>
#include <cuda_bf16.h>
#include <cstdint>

#define NH   12
#define SLEN 4096
#define HD   64
#define DIM  768
#define GRD  64

// ---------------- scratch ----------------------------------------------------
__device__ float g_Q[NH * SLEN * HD];
__device__ float g_K[NH * SLEN * HD];
__device__ float g_V[NH * SLEN * HD];
__device__ float g_relh[NH * SLEN * GRD];
__device__ float g_relw[NH * SLEN * GRD];
__device__ float g_ao[SLEN * DIM];

// split-bf16 operands (hi + lo ~ fp32)
__device__ __nv_bfloat16 g_Qh[NH * SLEN * HD];   // pre-scaled by 0.125
__device__ __nv_bfloat16 g_Ql[NH * SLEN * HD];
__device__ __nv_bfloat16 g_Kh[NH * SLEN * HD];
__device__ __nv_bfloat16 g_Kl[NH * SLEN * HD];
__device__ __nv_bfloat16 g_Vth[NH * HD * SLEN];  // transposed: [head][c][s]
__device__ __nv_bfloat16 g_Vtl[NH * HD * SLEN];

// ---------------- helpers -----------------------------------------------------
__device__ __forceinline__ uint32_t smem_u32(const void* p) {
    uint32_t a;
    asm("{ .reg .u64 t; cvta.to.shared.u64 t, %1; cvt.u32.u64 %0, t; }" : "=r"(a) : "l"(p));
    return a;
}

#define CP_ASYNC16(sm, gp) \
    asm volatile("cp.async.cg.shared.global [%0], [%1], 16;" :: "r"(sm), "l"(gp))
#define CP_COMMIT()  asm volatile("cp.async.commit_group;")
#define CP_WAIT1()   asm volatile("cp.async.wait_group 1;")
#define CP_WAIT0()   asm volatile("cp.async.wait_group 0;")

#define LDSM_X2(r0, r1, addr) \
    asm volatile("ldmatrix.sync.aligned.m8n8.x2.shared.b16 {%0,%1}, [%2];" \
                 : "=r"(r0), "=r"(r1) : "r"(addr))

#define MMA16816(d, a, b0, b1) \
    asm volatile("mma.sync.aligned.m16n8k16.row.col.f32.bf16.bf16.f32 " \
        "{%0,%1,%2,%3}, {%4,%5,%6,%7}, {%8,%9}, {%0,%1,%2,%3};" \
        : "+f"((d)[0]), "+f"((d)[1]), "+f"((d)[2]), "+f"((d)[3]) \
        : "r"((a)[0]), "r"((a)[1]), "r"((a)[2]), "r"((a)[3]), "r"(b0), "r"(b1))

__device__ __forceinline__ void split2(float x, float y, uint32_t& hi, uint32_t& lo) {
    __nv_bfloat162 h = __float22bfloat162_rn(make_float2(x, y));
    float rx = x - __low2float(h);
    float ry = y - __high2float(h);
    __nv_bfloat162 l = __float22bfloat162_rn(make_float2(rx, ry));
    hi = *reinterpret_cast<uint32_t*>(&h);
    lo = *reinterpret_cast<uint32_t*>(&l);
}

// ---------------- GEMM  C[M,N] = X[M,K] @ W[N,K]^T + b (SIMT, proven) --------
template <int EPI>
__global__ void gemm_nt(const float* __restrict__ Xin,
                        const float* __restrict__ W,
                        const float* __restrict__ bias,
                        float* __restrict__ out)
{
    const float* X = (EPI == 1) ? (const float*)g_ao : Xin;
    __shared__ float As[16][68];
    __shared__ float Bs[16][68];
    const int bm = blockIdx.y * 64;
    const int bn = blockIdx.x * 64;
    const int tid = threadIdx.x;
    const int tx = tid & 15, ty = tid >> 4;
    const int lr = tid >> 2, lk = (tid & 3) << 2;

    float acc[4][4] = {};
    for (int k0 = 0; k0 < DIM; k0 += 16) {
        float4 xa = *(const float4*)&X[(size_t)(bm + lr) * DIM + k0 + lk];
        As[lk + 0][lr] = xa.x; As[lk + 1][lr] = xa.y;
        As[lk + 2][lr] = xa.z; As[lk + 3][lr] = xa.w;
        float4 wb = *(const float4*)&W[(size_t)(bn + lr) * DIM + k0 + lk];
        Bs[lk + 0][lr] = wb.x; Bs[lk + 1][lr] = wb.y;
        Bs[lk + 2][lr] = wb.z; Bs[lk + 3][lr] = wb.w;
        __syncthreads();
#pragma unroll
        for (int kk = 0; kk < 16; kk++) {
            float4 a = *(const float4*)&As[kk][ty << 2];
            float4 b = *(const float4*)&Bs[kk][tx << 2];
            float av[4] = {a.x, a.y, a.z, a.w};
            float bv[4] = {b.x, b.y, b.z, b.w};
#pragma unroll
            for (int i = 0; i < 4; i++)
#pragma unroll
                for (int j = 0; j < 4; j++) acc[i][j] += av[i] * bv[j];
        }
        __syncthreads();
    }

    if (EPI == 0) {
        const int jbase = bn + (tx << 2);
        const int which = bn / DIM;
        const int head  = (bn % DIM) / HD;
        float* dst = (which == 0) ? g_Q : (which == 1) ? g_K : g_V;
#pragma unroll
        for (int i = 0; i < 4; i++) {
            const int s = bm + (ty << 2) + i;
#pragma unroll
            for (int j = 0; j < 4; j++) {
                const int jj = jbase + j;
                const int c  = jj & 63;
                dst[((size_t)head * SLEN + s) * HD + c] = acc[i][j] + bias[jj];
            }
        }
    } else {
#pragma unroll
        for (int i = 0; i < 4; i++) {
            const int s = bm + (ty << 2) + i;
#pragma unroll
            for (int j = 0; j < 4; j++) {
                const int jj = bn + (tx << 2) + j;
                out[(size_t)s * DIM + jj] = acc[i][j] + bias[jj];
            }
        }
    }
}

// ---------------- split-bf16 conversion --------------------------------------
__global__ void convert_kernel()
{
    for (size_t i = (size_t)blockIdx.x * 256 + threadIdx.x;
         i < (size_t)NH * SLEN * HD; i += (size_t)gridDim.x * 256) {
        float q = g_Q[i] * 0.125f;
        __nv_bfloat16 qh = __float2bfloat16(q);
        g_Qh[i] = qh;
        g_Ql[i] = __float2bfloat16(q - __bfloat162float(qh));
        float k = g_K[i];
        __nv_bfloat16 kh = __float2bfloat16(k);
        g_Kh[i] = kh;
        g_Kl[i] = __float2bfloat16(k - __bfloat162float(kh));
        float v = g_V[i];
        __nv_bfloat16 vh = __float2bfloat16(v);
        __nv_bfloat16 vl = __float2bfloat16(v - __bfloat162float(vh));
        int c = (int)(i & 63);
        size_t sh = i >> 6;
        int s = (int)(sh & 4095);
        int h = (int)(sh >> 12);
        size_t ti = ((size_t)h * HD + c) * SLEN + s;
        g_Vth[ti] = vh;
        g_Vtl[ti] = vl;
    }
}

// ---------------- rel-pos bias (proven in round 1) ---------------------------
#define REL_SM_FLOATS (64 * 68 + 127 * 65)
__global__ void rel_kernel(const float* __restrict__ relpos, int isW)
{
    extern __shared__ float sm[];
    float* Qs = sm;
    float* R  = sm + 64 * 68;
    const int qh = blockIdx.x, head = blockIdx.y;
    const int tid = threadIdx.x;
    const int tx = tid & 15, ty = tid >> 4;

    const float* Qg = &g_Q[((size_t)head * SLEN + qh * GRD) * HD];
    for (int t = tid; t < 4096; t += 256) {
        int c = t & 63, qw = t >> 6;
        Qs[c * 68 + qw] = Qg[(size_t)qw * HD + c];
    }

    if (!isW) {
        for (int t = tid; t < 4096; t += 256) {
            int c = t & 63, kh = t >> 6;
            R[c * 68 + kh] = relpos[(qh - kh + 63) * 64 + c];
        }
        __syncthreads();
        float acc[4][4] = {};
#pragma unroll 4
        for (int c = 0; c < 64; c++) {
            float4 a = *(const float4*)&Qs[c * 68 + (ty << 2)];
            float4 b = *(const float4*)&R[c * 68 + (tx << 2)];
            float av[4] = {a.x, a.y, a.z, a.w};
            float bv[4] = {b.x, b.y, b.z, b.w};
#pragma unroll
            for (int i = 0; i < 4; i++)
#pragma unroll
                for (int j = 0; j < 4; j++) acc[i][j] += av[i] * bv[j];
        }
#pragma unroll
        for (int i = 0; i < 4; i++)
#pragma unroll
            for (int j = 0; j < 4; j++) {
                int qw = (ty << 2) + i, kh = (tx << 2) + j;
                g_relh[((size_t)head * SLEN + qh * 64 + qw) * 64 + kh] = acc[i][j];
            }
    } else {
        for (int t = tid; t < 127 * 64; t += 256) {
            int c = t & 63, rr = t >> 6;
            R[rr * 65 + c] = relpos[rr * 64 + c];
        }
        __syncthreads();
        float acc[4][4] = {};
        const int qwb = ty << 2, kwb = tx << 2;
        for (int c = 0; c < 64; c++) {
            float4 a = *(const float4*)&Qs[c * 68 + qwb];
            float av[4] = {a.x, a.y, a.z, a.w};
#pragma unroll
            for (int i = 0; i < 4; i++)
#pragma unroll
                for (int j = 0; j < 4; j++)
                    acc[i][j] += av[i] * R[(qwb + i - kwb - j + 63) * 65 + c];
        }
#pragma unroll
        for (int i = 0; i < 4; i++)
#pragma unroll
            for (int j = 0; j < 4; j++) {
                int qw = qwb + i, kw = kwb + j;
                g_relw[((size_t)head * SLEN + qh * 64 + qw) * 64 + kw] = acc[i][j];
            }
    }
}

// ---------------- mma.sync flash attention -----------------------------------
// 256 threads = 8 warps; q-tile 128 (16 rows/warp); key-tile 64 = 1 key-grid row.
// Split bf16: S = QhKh + QhKl + QlKh ; O += PhVh + PhVl + PlVh.
// K/V smem tiles: 64 rows x 144B (padded) for conflict-free ldmatrix.
#define TROW     144                 // padded row stride (bytes) = 72 bf16
#define T_KH     0
#define T_KL     (64 * TROW)
#define T_VH     (2 * 64 * TROW)
#define T_VL     (3 * 64 * TROW)
#define STAGE_B  (4 * 64 * TROW)     // 36864
#define RH_OFF   (2 * STAGE_B)       // 73728
#define RW_OFF   (RH_OFF + 128 * 66 * 4)
#define SMEM_ATTN (RW_OFF + 128 * 66 * 4)   // 141312

__global__ void __launch_bounds__(256) attn_mma_kernel()
{
    extern __shared__ char smem[];
    const uint32_t sb = smem_u32(smem);
    const int tid  = threadIdx.x;
    const int lane = tid & 31;
    const int warp = tid >> 5;
    const int g    = lane >> 2;      // row within row-group
    const int tm   = lane & 3;
    const int head = blockIdx.y;
    const int q0   = blockIdx.x * 128;
    const int qr   = warp * 16;      // warp's first q row within tile

    float* rhS = (float*)(smem + RH_OFF);
    float* rwS = (float*)(smem + RW_OFF);

    // ---- rel tables into smem ----
    for (int t = tid; t < 8192; t += 256) {
        int row = t >> 6, k = t & 63;
        rhS[row * 66 + k] = g_relh[((size_t)head * SLEN + q0 + row) * 64 + k];
        rwS[row * 66 + k] = g_relw[((size_t)head * SLEN + q0 + row) * 64 + k];
    }

    // ---- Q fragments (persistent, registers) ----
    uint32_t qhf[4][4], qlf[4][4];
    {
        const uint32_t* q0h = (const uint32_t*)(g_Qh + ((size_t)head * SLEN + q0 + qr + g) * HD);
        const uint32_t* q1h = (const uint32_t*)(g_Qh + ((size_t)head * SLEN + q0 + qr + g + 8) * HD);
        const uint32_t* q0l = (const uint32_t*)(g_Ql + ((size_t)head * SLEN + q0 + qr + g) * HD);
        const uint32_t* q1l = (const uint32_t*)(g_Ql + ((size_t)head * SLEN + q0 + qr + g + 8) * HD);
#pragma unroll
        for (int ks = 0; ks < 4; ks++) {
            qhf[ks][0] = q0h[ks * 8 + tm];     qhf[ks][1] = q1h[ks * 8 + tm];
            qhf[ks][2] = q0h[ks * 8 + tm + 4]; qhf[ks][3] = q1h[ks * 8 + tm + 4];
            qlf[ks][0] = q0l[ks * 8 + tm];     qlf[ks][1] = q1l[ks * 8 + tm];
            qlf[ks][2] = q0l[ks * 8 + tm + 4]; qlf[ks][3] = q1l[ks * 8 + tm + 4];
        }
    }

    // per-thread ldmatrix row offset within a tile (lanes 16+ mirror 0-15)
    const uint32_t rowoff = (uint32_t)((lane & 7) * TROW + (((lane & 15) >> 3) << 4));

    float o[8][4];
#pragma unroll
    for (int cb = 0; cb < 8; cb++)
#pragma unroll
        for (int j = 0; j < 4; j++) o[cb][j] = 0.0f;
    float m0 = -1e30f, m1 = -1e30f, l0 = 0.0f, l1 = 0.0f;

    const char* KhG = (const char*)(g_Kh + (size_t)head * SLEN * HD);
    const char* KlG = (const char*)(g_Kl + (size_t)head * SLEN * HD);
    const char* VhG = (const char*)(g_Vth + (size_t)head * HD * SLEN);
    const char* VlG = (const char*)(g_Vtl + (size_t)head * HD * SLEN);

    // tile loader: 512 16B chunks per sub-tile, 2 per thread
    auto load_tiles = [&](int buf, int kt) {
        const uint32_t st = sb + buf * STAGE_B;
#pragma unroll
        for (int rep = 0; rep < 2; rep++) {
            int c = tid + rep * 256;
            int row = c >> 3, off = c & 7;
            // K rows: key-major, 128B payload
            CP_ASYNC16(st + T_KH + row * TROW + off * 16,
                       KhG + (size_t)(kt * 64 + row) * 128 + off * 16);
            CP_ASYNC16(st + T_KL + row * TROW + off * 16,
                       KlG + (size_t)(kt * 64 + row) * 128 + off * 16);
            // V^T rows: c-major, 64 keys * 2B = 128B payload
            CP_ASYNC16(st + T_VH + row * TROW + off * 16,
                       VhG + (size_t)row * 8192 + (size_t)kt * 128 + off * 16);
            CP_ASYNC16(st + T_VL + row * TROW + off * 16,
                       VlG + (size_t)row * 8192 + (size_t)kt * 128 + off * 16);
        }
    };

    load_tiles(0, 0);
    CP_COMMIT();

    for (int kt = 0; kt < 64; kt++) {
        if (kt < 63) { load_tiles((kt + 1) & 1, kt + 1); CP_COMMIT(); CP_WAIT1(); }
        else         { CP_WAIT0(); }
        __syncthreads();

        const uint32_t st  = sb + (kt & 1) * STAGE_B;
        const uint32_t kh0 = st + T_KH + rowoff;
        const uint32_t kl0 = st + T_KL + rowoff;
        const uint32_t vh0 = st + T_VH + rowoff;
        const uint32_t vl0 = st + T_VL + rowoff;

        // ---- S = Qh Kh + Qh Kl + Ql Kh ----
        float sc[8][4];
#pragma unroll
        for (int nb = 0; nb < 8; nb++)
#pragma unroll
            for (int j = 0; j < 4; j++) sc[nb][j] = 0.0f;

#pragma unroll
        for (int ks = 0; ks < 4; ks++) {
#pragma unroll
            for (int nb = 0; nb < 8; nb++) {
                uint32_t bh0, bh1, bl0, bl1;
                LDSM_X2(bh0, bh1, kh0 + nb * (8 * TROW) + ks * 32);
                LDSM_X2(bl0, bl1, kl0 + nb * (8 * TROW) + ks * 32);
                MMA16816(sc[nb], qhf[ks], bh0, bh1);
                MMA16816(sc[nb], qhf[ks], bl0, bl1);
                MMA16816(sc[nb], qlf[ks], bh0, bh1);
            }
        }

        // ---- bias + online softmax (rows r0 = qr+g, r1 = r0+8) ----
        const int r0 = qr + g, r1 = r0 + 8;
        const float rh0 = rhS[r0 * 66 + kt];
        const float rh1 = rhS[r1 * 66 + kt];
        float mt0 = -1e30f, mt1 = -1e30f;
#pragma unroll
        for (int nb = 0; nb < 8; nb++) {
            float2 w0 = *(const float2*)&rwS[r0 * 66 + nb * 8 + tm * 2];
            float2 w1 = *(const float2*)&rwS[r1 * 66 + nb * 8 + tm * 2];
            sc[nb][0] += rh0 + w0.x;  sc[nb][1] += rh0 + w0.y;
            sc[nb][2] += rh1 + w1.x;  sc[nb][3] += rh1 + w1.y;
            mt0 = fmaxf(mt0, fmaxf(sc[nb][0], sc[nb][1]));
            mt1 = fmaxf(mt1, fmaxf(sc[nb][2], sc[nb][3]));
        }
        mt0 = fmaxf(mt0, __shfl_xor_sync(0xffffffffu, mt0, 1));
        mt0 = fmaxf(mt0, __shfl_xor_sync(0xffffffffu, mt0, 2));
        mt1 = fmaxf(mt1, __shfl_xor_sync(0xffffffffu, mt1, 1));
        mt1 = fmaxf(mt1, __shfl_xor_sync(0xffffffffu, mt1, 2));

        const float mn0 = fmaxf(m0, mt0);
        const float mn1 = fmaxf(m1, mt1);
        const float a0 = __expf(m0 - mn0);
        const float a1 = __expf(m1 - mn1);
        m0 = mn0; m1 = mn1;

        float s0 = 0.0f, s1 = 0.0f;
#pragma unroll
        for (int nb = 0; nb < 8; nb++) {
            sc[nb][0] = __expf(sc[nb][0] - mn0);
            sc[nb][1] = __expf(sc[nb][1] - mn0);
            sc[nb][2] = __expf(sc[nb][2] - mn1);
            sc[nb][3] = __expf(sc[nb][3] - mn1);
            s0 += sc[nb][0] + sc[nb][1];
            s1 += sc[nb][2] + sc[nb][3];
        }
        s0 += __shfl_xor_sync(0xffffffffu, s0, 1);
        s0 += __shfl_xor_sync(0xffffffffu, s0, 2);
        s1 += __shfl_xor_sync(0xffffffffu, s1, 1);
        s1 += __shfl_xor_sync(0xffffffffu, s1, 2);
        l0 = l0 * a0 + s0;
        l1 = l1 * a1 + s1;

        // rescale O
#pragma unroll
        for (int cb = 0; cb < 8; cb++) {
            o[cb][0] *= a0; o[cb][1] *= a0;
            o[cb][2] *= a1; o[cb][3] *= a1;
        }

        // ---- O += Ph Vh + Ph Vl + Pl Vh ----
#pragma unroll
        for (int kb = 0; kb < 4; kb++) {
            uint32_t ph[4], pl[4];
            split2(sc[2 * kb][0],     sc[2 * kb][1],     ph[0], pl[0]);
            split2(sc[2 * kb][2],     sc[2 * kb][3],     ph[1], pl[1]);
            split2(sc[2 * kb + 1][0], sc[2 * kb + 1][1], ph[2], pl[2]);
            split2(sc[2 * kb + 1][2], sc[2 * kb + 1][3], ph[3], pl[3]);
#pragma unroll
            for (int cb = 0; cb < 8; cb++) {
                uint32_t bh0, bh1, bl0, bl1;
                LDSM_X2(bh0, bh1, vh0 + cb * (8 * TROW) + kb * 32);
                LDSM_X2(bl0, bl1, vl0 + cb * (8 * TROW) + kb * 32);
                MMA16816(o[cb], ph, bh0, bh1);
                MMA16816(o[cb], ph, bl0, bl1);
                MMA16816(o[cb], pl, bh0, bh1);
            }
        }
        __syncthreads();
    }

    // ---- normalize + write ----
    const float i0 = 1.0f / l0;
    const float i1 = 1.0f / l1;
    float* d0 = &g_ao[(size_t)(q0 + qr + g) * DIM + head * HD];
    float* d1 = &g_ao[(size_t)(q0 + qr + g + 8) * DIM + head * HD];
#pragma unroll
    for (int cb = 0; cb < 8; cb++) {
        const int col = cb * 8 + tm * 2;
        *(float2*)(d0 + col) = make_float2(o[cb][0] * i0, o[cb][1] * i0);
        *(float2*)(d1 + col) = make_float2(o[cb][2] * i1, o[cb][3] * i1);
    }
}

// ---------------- launch ------------------------------------------------------
extern "C" void kernel_launch(void* const* d_in, const int* in_sizes, int n_in,
                              void* d_out, int out_size)
{
    const float* x      = (const float*)d_in[0];
    const float* qkv_w  = (const float*)d_in[1];
    const float* qkv_b  = (const float*)d_in[2];
    const float* proj_w = (const float*)d_in[3];
    const float* proj_b = (const float*)d_in[4];
    const float* rph    = (const float*)d_in[5];
    const float* rpw    = (const float*)d_in[6];
    float* out = (float*)d_out;

    const int rel_sm = REL_SM_FLOATS * (int)sizeof(float);
    cudaFuncSetAttribute(rel_kernel, cudaFuncAttributeMaxDynamicSharedMemorySize, rel_sm);
    cudaFuncSetAttribute(attn_mma_kernel, cudaFuncAttributeMaxDynamicSharedMemorySize, SMEM_ATTN);

    // 1) qkv = x @ qkv_w^T + b  ->  Q,K,V (fp32; q unscaled)
    gemm_nt<0><<<dim3(3 * DIM / 64, SLEN / 64), 256>>>(x, qkv_w, qkv_b, nullptr);

    // 2) split-bf16 operands (Q pre-scaled by 0.125; V transposed)
    convert_kernel<<<3072, 256>>>();

    // 3) decomposed rel-pos bias tables (from fp32 Q, unscaled per reference)
    rel_kernel<<<dim3(GRD, NH), 256, rel_sm>>>(rph, 0);
    rel_kernel<<<dim3(GRD, NH), 256, rel_sm>>>(rpw, 1);

    // 4) mma.sync flash attention with fused rel bias
    attn_mma_kernel<<<dim3(SLEN / 128, NH), 256, SMEM_ATTN>>>();

    // 5) out = attn_out @ proj_w^T + b
    gemm_nt<1><<<dim3(DIM / 64, SLEN / 64), 256>>>(nullptr, proj_w, proj_b, out);
}

// round 4
// speedup vs baseline: 3.0672x; 1.4916x over previous
#include <cuda_runtime.h>
#include <cuda_bf16.h>
#include <cstdint>

#define NH   12
#define SLEN 4096
#define HD   64
#define DIM  768
#define GRD  64

// ---------------- scratch ----------------------------------------------------
__device__ float g_relh[NH * SLEN * GRD];
__device__ float g_relw[NH * SLEN * GRD];

// split-bf16 operands (hi + lo ~ fp32)
__device__ __nv_bfloat16 g_Qh[NH * SLEN * HD];   // pre-scaled by 0.125
__device__ __nv_bfloat16 g_Ql[NH * SLEN * HD];
__device__ __nv_bfloat16 g_Kh[NH * SLEN * HD];
__device__ __nv_bfloat16 g_Kl[NH * SLEN * HD];
__device__ __nv_bfloat16 g_Vth[NH * HD * SLEN];  // transposed: [head][c][s]
__device__ __nv_bfloat16 g_Vtl[NH * HD * SLEN];

__device__ __nv_bfloat16 g_Xh[SLEN * DIM];       // x split
__device__ __nv_bfloat16 g_Xl[SLEN * DIM];
__device__ __nv_bfloat16 g_W1h[3 * DIM * DIM];   // qkv_w split
__device__ __nv_bfloat16 g_W1l[3 * DIM * DIM];
__device__ __nv_bfloat16 g_W2h[DIM * DIM];       // proj_w split
__device__ __nv_bfloat16 g_W2l[DIM * DIM];
__device__ __nv_bfloat16 g_aoh[SLEN * DIM];      // attention out split
__device__ __nv_bfloat16 g_aol[SLEN * DIM];

// ---------------- helpers -----------------------------------------------------
__device__ __forceinline__ uint32_t smem_u32(const void* p) {
    uint32_t a;
    asm("{ .reg .u64 t; cvta.to.shared.u64 t, %1; cvt.u32.u64 %0, t; }" : "=r"(a) : "l"(p));
    return a;
}

#define CP_ASYNC16(sm, gp) \
    asm volatile("cp.async.cg.shared.global [%0], [%1], 16;" :: "r"(sm), "l"(gp))
#define CP_COMMIT()  asm volatile("cp.async.commit_group;")
#define CP_WAIT1()   asm volatile("cp.async.wait_group 1;")
#define CP_WAIT0()   asm volatile("cp.async.wait_group 0;")

#define LDSM_X2(r0, r1, addr) \
    asm volatile("ldmatrix.sync.aligned.m8n8.x2.shared.b16 {%0,%1}, [%2];" \
                 : "=r"(r0), "=r"(r1) : "r"(addr))
#define LDSM_X4(r0, r1, r2, r3, addr) \
    asm volatile("ldmatrix.sync.aligned.m8n8.x4.shared.b16 {%0,%1,%2,%3}, [%4];" \
                 : "=r"(r0), "=r"(r1), "=r"(r2), "=r"(r3) : "r"(addr))

#define MMA16816(d, a, b0, b1) \
    asm volatile("mma.sync.aligned.m16n8k16.row.col.f32.bf16.bf16.f32 " \
        "{%0,%1,%2,%3}, {%4,%5,%6,%7}, {%8,%9}, {%0,%1,%2,%3};" \
        : "+f"((d)[0]), "+f"((d)[1]), "+f"((d)[2]), "+f"((d)[3]) \
        : "r"((a)[0]), "r"((a)[1]), "r"((a)[2]), "r"((a)[3]), "r"(b0), "r"(b1))

__device__ __forceinline__ void split2(float x, float y, uint32_t& hi, uint32_t& lo) {
    __nv_bfloat162 h = __float22bfloat162_rn(make_float2(x, y));
    float rx = x - __low2float(h);
    float ry = y - __high2float(h);
    __nv_bfloat162 l = __float22bfloat162_rn(make_float2(rx, ry));
    hi = *reinterpret_cast<uint32_t*>(&h);
    lo = *reinterpret_cast<uint32_t*>(&l);
}

// ---------------- input conversion (x, qkv_w, proj_w -> split bf16) ----------
#define NX (SLEN * DIM)
#define NW1 (3 * DIM * DIM)
#define NW2 (DIM * DIM)
__global__ void convert_in(const float* __restrict__ x,
                           const float* __restrict__ w1,
                           const float* __restrict__ w2)
{
    for (size_t i = (size_t)blockIdx.x * 256 + threadIdx.x;
         i < (size_t)(NX + NW1 + NW2); i += (size_t)gridDim.x * 256) {
        float v; __nv_bfloat16 *dh, *dl; size_t j;
        if (i < NX)            { j = i;             v = x[j];  dh = g_Xh;  dl = g_Xl;  }
        else if (i < NX + NW1) { j = i - NX;        v = w1[j]; dh = g_W1h; dl = g_W1l; }
        else                   { j = i - NX - NW1;  v = w2[j]; dh = g_W2h; dl = g_W2l; }
        __nv_bfloat16 h = __float2bfloat16(v);
        dh[j] = h;
        dl[j] = __float2bfloat16(v - __bfloat162float(h));
    }
}

// ---------------- split-bf16 tensor GEMM -------------------------------------
// C[M,N] = A[M,768] @ B[N,768]^T (+bias). BM=128, BN=64, BK=32, 256 thr.
// MODE 0: qkv epilogue (scatter split Q/K/V). MODE 1: proj (fp32 out + bias).
#define TG 80                       // padded row stride bytes (64B + 16)
#define G_AH 0
#define G_AL (128 * TG)
#define G_BH (2 * 128 * TG)
#define G_BL (2 * 128 * TG + 64 * TG)
#define G_STG (2 * 128 * TG + 2 * 64 * TG)   // 30720
#define SMEM_GEMM (2 * G_STG)                // 61440

template <int MODE>
__global__ void __launch_bounds__(256) gemm_bf16(
    const __nv_bfloat16* __restrict__ Agh, const __nv_bfloat16* __restrict__ Agl,
    const __nv_bfloat16* __restrict__ Bgh, const __nv_bfloat16* __restrict__ Bgl,
    const float* __restrict__ bias, float* __restrict__ out)
{
    extern __shared__ char smem[];
    const uint32_t sb = smem_u32(smem);
    const int tid  = threadIdx.x;
    const int lane = tid & 31;
    const int warp = tid >> 5;
    const int g    = lane >> 2;
    const int tm   = lane & 3;
    const int bm   = blockIdx.y * 128;
    const int bn   = blockIdx.x * 64;
    const int qr   = warp * 16;

    auto load_tile = [&](int buf, int kt) {
        const uint32_t st = sb + buf * G_STG;
        const int k0 = kt * 32;
#pragma unroll
        for (int rep = 0; rep < 6; rep++) {
            int c = tid + rep * 256;            // 1536 chunks
            if (c < 512) {                      // A hi: 128 rows x 4 chunks
                int row = c >> 2, off = c & 3;
                CP_ASYNC16(st + G_AH + row * TG + off * 16,
                           Agh + (size_t)(bm + row) * DIM + k0 + off * 8);
            } else if (c < 1024) {
                int cc = c - 512, row = cc >> 2, off = cc & 3;
                CP_ASYNC16(st + G_AL + row * TG + off * 16,
                           Agl + (size_t)(bm + row) * DIM + k0 + off * 8);
            } else if (c < 1280) {
                int cc = c - 1024, row = cc >> 2, off = cc & 3;
                CP_ASYNC16(st + G_BH + row * TG + off * 16,
                           Bgh + (size_t)(bn + row) * DIM + k0 + off * 8);
            } else {
                int cc = c - 1280, row = cc >> 2, off = cc & 3;
                CP_ASYNC16(st + G_BL + row * TG + off * 16,
                           Bgl + (size_t)(bn + row) * DIM + k0 + off * 8);
            }
        }
    };

    const uint32_t arow = (uint32_t)((lane & 15) * TG + (lane >> 4) * 16) + qr * TG;
    const uint32_t brow = (uint32_t)((lane & 7) * TG + (((lane & 15) >> 3) << 4));

    float sc[8][4];
#pragma unroll
    for (int nb = 0; nb < 8; nb++)
#pragma unroll
        for (int j = 0; j < 4; j++) sc[nb][j] = 0.0f;

    load_tile(0, 0);
    CP_COMMIT();

    for (int kt = 0; kt < 24; kt++) {
        if (kt < 23) { load_tile((kt + 1) & 1, kt + 1); CP_COMMIT(); CP_WAIT1(); }
        else         { CP_WAIT0(); }
        __syncthreads();

        const uint32_t st = sb + (kt & 1) * G_STG;
#pragma unroll
        for (int ks = 0; ks < 2; ks++) {
            uint32_t ah[4], al[4];
            LDSM_X4(ah[0], ah[1], ah[2], ah[3], st + G_AH + arow + ks * 32);
            LDSM_X4(al[0], al[1], al[2], al[3], st + G_AL + arow + ks * 32);
#pragma unroll
            for (int nb = 0; nb < 8; nb++) {
                uint32_t bh0, bh1, bl0, bl1;
                LDSM_X2(bh0, bh1, st + G_BH + brow + nb * (8 * TG) + ks * 32);
                LDSM_X2(bl0, bl1, st + G_BL + brow + nb * (8 * TG) + ks * 32);
                MMA16816(sc[nb], ah, bh0, bh1);
                MMA16816(sc[nb], ah, bl0, bl1);
                MMA16816(sc[nb], al, bh0, bh1);
            }
        }
        __syncthreads();
    }

    // ---- epilogue ----
    const int r0 = bm + qr + g, r1 = r0 + 8;
    if (MODE == 1) {
#pragma unroll
        for (int nb = 0; nb < 8; nb++) {
            const int jj = bn + nb * 8 + tm * 2;
            const float b0 = bias[jj], b1 = bias[jj + 1];
            *(float2*)&out[(size_t)r0 * DIM + jj] = make_float2(sc[nb][0] + b0, sc[nb][1] + b1);
            *(float2*)&out[(size_t)r1 * DIM + jj] = make_float2(sc[nb][2] + b0, sc[nb][3] + b1);
        }
    } else {
        const int which = bn / DIM;
        const int head  = (bn % DIM) >> 6;
#pragma unroll
        for (int nb = 0; nb < 8; nb++) {
            const int jj  = bn + nb * 8 + tm * 2;
            const int col = nb * 8 + tm * 2;
            const float b0 = bias[jj], b1 = bias[jj + 1];
            float v00 = sc[nb][0] + b0, v01 = sc[nb][1] + b1;
            float v10 = sc[nb][2] + b0, v11 = sc[nb][3] + b1;
            if (which == 0) {
                uint32_t h, l;
                split2(v00 * 0.125f, v01 * 0.125f, h, l);
                *(uint32_t*)&g_Qh[((size_t)head * SLEN + r0) * HD + col] = h;
                *(uint32_t*)&g_Ql[((size_t)head * SLEN + r0) * HD + col] = l;
                split2(v10 * 0.125f, v11 * 0.125f, h, l);
                *(uint32_t*)&g_Qh[((size_t)head * SLEN + r1) * HD + col] = h;
                *(uint32_t*)&g_Ql[((size_t)head * SLEN + r1) * HD + col] = l;
            } else if (which == 1) {
                uint32_t h, l;
                split2(v00, v01, h, l);
                *(uint32_t*)&g_Kh[((size_t)head * SLEN + r0) * HD + col] = h;
                *(uint32_t*)&g_Kl[((size_t)head * SLEN + r0) * HD + col] = l;
                split2(v10, v11, h, l);
                *(uint32_t*)&g_Kh[((size_t)head * SLEN + r1) * HD + col] = h;
                *(uint32_t*)&g_Kl[((size_t)head * SLEN + r1) * HD + col] = l;
            } else {
                // V transposed: [head][c][s]
                float vv[4] = {v00, v01, v10, v11};
                int rr[4] = {r0, r0, r1, r1};
                int cc[4] = {col, col + 1, col, col + 1};
#pragma unroll
                for (int e = 0; e < 4; e++) {
                    __nv_bfloat16 h = __float2bfloat16(vv[e]);
                    size_t ti = ((size_t)head * HD + cc[e]) * SLEN + rr[e];
                    g_Vth[ti] = h;
                    g_Vtl[ti] = __float2bfloat16(vv[e] - __bfloat162float(h));
                }
            }
        }
    }
}

// ---------------- rel-pos bias (merged h/w; Q from split) --------------------
#define REL_SM_FLOATS (64 * 68 + 127 * 65)
__global__ void rel_kernel(const float* __restrict__ rph,
                           const float* __restrict__ rpw)
{
    extern __shared__ float sm[];
    float* Qs = sm;
    float* R  = sm + 64 * 68;
    const int qh = blockIdx.x, head = blockIdx.y;
    const int isW = blockIdx.z;
    const float* relpos = isW ? rpw : rph;
    const int tid = threadIdx.x;
    const int tx = tid & 15, ty = tid >> 4;

    const __nv_bfloat16* Qhg = &g_Qh[((size_t)head * SLEN + qh * GRD) * HD];
    const __nv_bfloat16* Qlg = &g_Ql[((size_t)head * SLEN + qh * GRD) * HD];
    for (int t = tid; t < 4096; t += 256) {
        int c = t & 63, qw = t >> 6;
        Qs[c * 68 + qw] = 8.0f * (__bfloat162float(Qhg[(size_t)qw * HD + c]) +
                                  __bfloat162float(Qlg[(size_t)qw * HD + c]));
    }

    if (!isW) {
        for (int t = tid; t < 4096; t += 256) {
            int c = t & 63, kh = t >> 6;
            R[c * 68 + kh] = relpos[(qh - kh + 63) * 64 + c];
        }
        __syncthreads();
        float acc[4][4] = {};
#pragma unroll 4
        for (int c = 0; c < 64; c++) {
            float4 a = *(const float4*)&Qs[c * 68 + (ty << 2)];
            float4 b = *(const float4*)&R[c * 68 + (tx << 2)];
            float av[4] = {a.x, a.y, a.z, a.w};
            float bv[4] = {b.x, b.y, b.z, b.w};
#pragma unroll
            for (int i = 0; i < 4; i++)
#pragma unroll
                for (int j = 0; j < 4; j++) acc[i][j] += av[i] * bv[j];
        }
#pragma unroll
        for (int i = 0; i < 4; i++)
#pragma unroll
            for (int j = 0; j < 4; j++) {
                int qw = (ty << 2) + i, kh = (tx << 2) + j;
                g_relh[((size_t)head * SLEN + qh * 64 + qw) * 64 + kh] = acc[i][j];
            }
    } else {
        for (int t = tid; t < 127 * 64; t += 256) {
            int c = t & 63, rr = t >> 6;
            R[rr * 65 + c] = relpos[rr * 64 + c];
        }
        __syncthreads();
        float acc[4][4] = {};
        const int qwb = ty << 2, kwb = tx << 2;
        for (int c = 0; c < 64; c++) {
            float4 a = *(const float4*)&Qs[c * 68 + qwb];
            float av[4] = {a.x, a.y, a.z, a.w};
#pragma unroll
            for (int i = 0; i < 4; i++)
#pragma unroll
                for (int j = 0; j < 4; j++)
                    acc[i][j] += av[i] * R[(qwb + i - kwb - j + 63) * 65 + c];
        }
#pragma unroll
        for (int i = 0; i < 4; i++)
#pragma unroll
            for (int j = 0; j < 4; j++) {
                int qw = qwb + i, kw = kwb + j;
                g_relw[((size_t)head * SLEN + qh * 64 + qw) * 64 + kw] = acc[i][j];
            }
    }
}

// ---------------- mma.sync flash attention (proven round 3) ------------------
#define TROW     144
#define T_KH     0
#define T_KL     (64 * TROW)
#define T_VH     (2 * 64 * TROW)
#define T_VL     (3 * 64 * TROW)
#define STAGE_B  (4 * 64 * TROW)
#define RH_OFF   (2 * STAGE_B)
#define RW_OFF   (RH_OFF + 128 * 66 * 4)
#define SMEM_ATTN (RW_OFF + 128 * 66 * 4)

__global__ void __launch_bounds__(256) attn_mma_kernel()
{
    extern __shared__ char smem[];
    const uint32_t sb = smem_u32(smem);
    const int tid  = threadIdx.x;
    const int lane = tid & 31;
    const int warp = tid >> 5;
    const int g    = lane >> 2;
    const int tm   = lane & 3;
    const int head = blockIdx.y;
    const int q0   = blockIdx.x * 128;
    const int qr   = warp * 16;

    float* rhS = (float*)(smem + RH_OFF);
    float* rwS = (float*)(smem + RW_OFF);

    for (int t = tid; t < 8192; t += 256) {
        int row = t >> 6, k = t & 63;
        rhS[row * 66 + k] = g_relh[((size_t)head * SLEN + q0 + row) * 64 + k];
        rwS[row * 66 + k] = g_relw[((size_t)head * SLEN + q0 + row) * 64 + k];
    }

    uint32_t qhf[4][4], qlf[4][4];
    {
        const uint32_t* q0h = (const uint32_t*)(g_Qh + ((size_t)head * SLEN + q0 + qr + g) * HD);
        const uint32_t* q1h = (const uint32_t*)(g_Qh + ((size_t)head * SLEN + q0 + qr + g + 8) * HD);
        const uint32_t* q0l = (const uint32_t*)(g_Ql + ((size_t)head * SLEN + q0 + qr + g) * HD);
        const uint32_t* q1l = (const uint32_t*)(g_Ql + ((size_t)head * SLEN + q0 + qr + g + 8) * HD);
#pragma unroll
        for (int ks = 0; ks < 4; ks++) {
            qhf[ks][0] = q0h[ks * 8 + tm];     qhf[ks][1] = q1h[ks * 8 + tm];
            qhf[ks][2] = q0h[ks * 8 + tm + 4]; qhf[ks][3] = q1h[ks * 8 + tm + 4];
            qlf[ks][0] = q0l[ks * 8 + tm];     qlf[ks][1] = q1l[ks * 8 + tm];
            qlf[ks][2] = q0l[ks * 8 + tm + 4]; qlf[ks][3] = q1l[ks * 8 + tm + 4];
        }
    }

    const uint32_t rowoff = (uint32_t)((lane & 7) * TROW + (((lane & 15) >> 3) << 4));

    float o[8][4];
#pragma unroll
    for (int cb = 0; cb < 8; cb++)
#pragma unroll
        for (int j = 0; j < 4; j++) o[cb][j] = 0.0f;
    float m0 = -1e30f, m1 = -1e30f, l0 = 0.0f, l1 = 0.0f;

    const char* KhG = (const char*)(g_Kh + (size_t)head * SLEN * HD);
    const char* KlG = (const char*)(g_Kl + (size_t)head * SLEN * HD);
    const char* VhG = (const char*)(g_Vth + (size_t)head * HD * SLEN);
    const char* VlG = (const char*)(g_Vtl + (size_t)head * HD * SLEN);

    auto load_tiles = [&](int buf, int kt) {
        const uint32_t st = sb + buf * STAGE_B;
#pragma unroll
        for (int rep = 0; rep < 2; rep++) {
            int c = tid + rep * 256;
            int row = c >> 3, off = c & 7;
            CP_ASYNC16(st + T_KH + row * TROW + off * 16,
                       KhG + (size_t)(kt * 64 + row) * 128 + off * 16);
            CP_ASYNC16(st + T_KL + row * TROW + off * 16,
                       KlG + (size_t)(kt * 64 + row) * 128 + off * 16);
            CP_ASYNC16(st + T_VH + row * TROW + off * 16,
                       VhG + (size_t)row * 8192 + (size_t)kt * 128 + off * 16);
            CP_ASYNC16(st + T_VL + row * TROW + off * 16,
                       VlG + (size_t)row * 8192 + (size_t)kt * 128 + off * 16);
        }
    };

    load_tiles(0, 0);
    CP_COMMIT();

    for (int kt = 0; kt < 64; kt++) {
        if (kt < 63) { load_tiles((kt + 1) & 1, kt + 1); CP_COMMIT(); CP_WAIT1(); }
        else         { CP_WAIT0(); }
        __syncthreads();

        const uint32_t st  = sb + (kt & 1) * STAGE_B;
        const uint32_t kh0 = st + T_KH + rowoff;
        const uint32_t kl0 = st + T_KL + rowoff;
        const uint32_t vh0 = st + T_VH + rowoff;
        const uint32_t vl0 = st + T_VL + rowoff;

        float sc[8][4];
#pragma unroll
        for (int nb = 0; nb < 8; nb++)
#pragma unroll
            for (int j = 0; j < 4; j++) sc[nb][j] = 0.0f;

#pragma unroll
        for (int ks = 0; ks < 4; ks++) {
#pragma unroll
            for (int nb = 0; nb < 8; nb++) {
                uint32_t bh0, bh1, bl0, bl1;
                LDSM_X2(bh0, bh1, kh0 + nb * (8 * TROW) + ks * 32);
                LDSM_X2(bl0, bl1, kl0 + nb * (8 * TROW) + ks * 32);
                MMA16816(sc[nb], qhf[ks], bh0, bh1);
                MMA16816(sc[nb], qhf[ks], bl0, bl1);
                MMA16816(sc[nb], qlf[ks], bh0, bh1);
            }
        }

        const int r0 = qr + g, r1 = r0 + 8;
        const float rh0 = rhS[r0 * 66 + kt];
        const float rh1 = rhS[r1 * 66 + kt];
        float mt0 = -1e30f, mt1 = -1e30f;
#pragma unroll
        for (int nb = 0; nb < 8; nb++) {
            float2 w0 = *(const float2*)&rwS[r0 * 66 + nb * 8 + tm * 2];
            float2 w1 = *(const float2*)&rwS[r1 * 66 + nb * 8 + tm * 2];
            sc[nb][0] += rh0 + w0.x;  sc[nb][1] += rh0 + w0.y;
            sc[nb][2] += rh1 + w1.x;  sc[nb][3] += rh1 + w1.y;
            mt0 = fmaxf(mt0, fmaxf(sc[nb][0], sc[nb][1]));
            mt1 = fmaxf(mt1, fmaxf(sc[nb][2], sc[nb][3]));
        }
        mt0 = fmaxf(mt0, __shfl_xor_sync(0xffffffffu, mt0, 1));
        mt0 = fmaxf(mt0, __shfl_xor_sync(0xffffffffu, mt0, 2));
        mt1 = fmaxf(mt1, __shfl_xor_sync(0xffffffffu, mt1, 1));
        mt1 = fmaxf(mt1, __shfl_xor_sync(0xffffffffu, mt1, 2));

        const float mn0 = fmaxf(m0, mt0);
        const float mn1 = fmaxf(m1, mt1);
        const float a0 = __expf(m0 - mn0);
        const float a1 = __expf(m1 - mn1);
        m0 = mn0; m1 = mn1;

        float s0 = 0.0f, s1 = 0.0f;
#pragma unroll
        for (int nb = 0; nb < 8; nb++) {
            sc[nb][0] = __expf(sc[nb][0] - mn0);
            sc[nb][1] = __expf(sc[nb][1] - mn0);
            sc[nb][2] = __expf(sc[nb][2] - mn1);
            sc[nb][3] = __expf(sc[nb][3] - mn1);
            s0 += sc[nb][0] + sc[nb][1];
            s1 += sc[nb][2] + sc[nb][3];
        }
        s0 += __shfl_xor_sync(0xffffffffu, s0, 1);
        s0 += __shfl_xor_sync(0xffffffffu, s0, 2);
        s1 += __shfl_xor_sync(0xffffffffu, s1, 1);
        s1 += __shfl_xor_sync(0xffffffffu, s1, 2);
        l0 = l0 * a0 + s0;
        l1 = l1 * a1 + s1;

#pragma unroll
        for (int cb = 0; cb < 8; cb++) {
            o[cb][0] *= a0; o[cb][1] *= a0;
            o[cb][2] *= a1; o[cb][3] *= a1;
        }

#pragma unroll
        for (int kb = 0; kb < 4; kb++) {
            uint32_t ph[4], pl[4];
            split2(sc[2 * kb][0],     sc[2 * kb][1],     ph[0], pl[0]);
            split2(sc[2 * kb][2],     sc[2 * kb][3],     ph[1], pl[1]);
            split2(sc[2 * kb + 1][0], sc[2 * kb + 1][1], ph[2], pl[2]);
            split2(sc[2 * kb + 1][2], sc[2 * kb + 1][3], ph[3], pl[3]);
#pragma unroll
            for (int cb = 0; cb < 8; cb++) {
                uint32_t bh0, bh1, bl0, bl1;
                LDSM_X2(bh0, bh1, vh0 + cb * (8 * TROW) + kb * 32);
                LDSM_X2(bl0, bl1, vl0 + cb * (8 * TROW) + kb * 32);
                MMA16816(o[cb], ph, bh0, bh1);
                MMA16816(o[cb], ph, bl0, bl1);
                MMA16816(o[cb], pl, bh0, bh1);
            }
        }
        __syncthreads();
    }

    // ---- normalize + write split-bf16 attention output ----
    const float i0 = 1.0f / l0;
    const float i1 = 1.0f / l1;
    const size_t o0 = (size_t)(q0 + qr + g) * DIM + head * HD;
    const size_t o1 = (size_t)(q0 + qr + g + 8) * DIM + head * HD;
#pragma unroll
    for (int cb = 0; cb < 8; cb++) {
        const int col = cb * 8 + tm * 2;
        uint32_t h, l;
        split2(o[cb][0] * i0, o[cb][1] * i0, h, l);
        *(uint32_t*)&g_aoh[o0 + col] = h;
        *(uint32_t*)&g_aol[o0 + col] = l;
        split2(o[cb][2] * i1, o[cb][3] * i1, h, l);
        *(uint32_t*)&g_aoh[o1 + col] = h;
        *(uint32_t*)&g_aol[o1 + col] = l;
    }
}

// ---------------- launch ------------------------------------------------------
extern "C" void kernel_launch(void* const* d_in, const int* in_sizes, int n_in,
                              void* d_out, int out_size)
{
    const float* x      = (const float*)d_in[0];
    const float* qkv_w  = (const float*)d_in[1];
    const float* qkv_b  = (const float*)d_in[2];
    const float* proj_w = (const float*)d_in[3];
    const float* proj_b = (const float*)d_in[4];
    const float* rph    = (const float*)d_in[5];
    const float* rpw    = (const float*)d_in[6];
    float* out = (float*)d_out;

    const int rel_sm = REL_SM_FLOATS * (int)sizeof(float);
    cudaFuncSetAttribute(rel_kernel, cudaFuncAttributeMaxDynamicSharedMemorySize, rel_sm);
    cudaFuncSetAttribute(attn_mma_kernel, cudaFuncAttributeMaxDynamicSharedMemorySize, SMEM_ATTN);
    cudaFuncSetAttribute(gemm_bf16<0>, cudaFuncAttributeMaxDynamicSharedMemorySize, SMEM_GEMM);
    cudaFuncSetAttribute(gemm_bf16<1>, cudaFuncAttributeMaxDynamicSharedMemorySize, SMEM_GEMM);

    __nv_bfloat16 *Xh, *Xl, *W1h, *W1l, *W2h, *W2l, *AOh, *AOl;
    cudaGetSymbolAddress((void**)&Xh,  g_Xh);
    cudaGetSymbolAddress((void**)&Xl,  g_Xl);
    cudaGetSymbolAddress((void**)&W1h, g_W1h);
    cudaGetSymbolAddress((void**)&W1l, g_W1l);
    cudaGetSymbolAddress((void**)&W2h, g_W2h);
    cudaGetSymbolAddress((void**)&W2l, g_W2l);
    cudaGetSymbolAddress((void**)&AOh, g_aoh);
    cudaGetSymbolAddress((void**)&AOl, g_aol);

    // 1) split inputs to bf16 hi/lo
    convert_in<<<2048, 256>>>(x, qkv_w, proj_w);

    // 2) qkv GEMM (tensor) -> split Q/K/V (Q pre-scaled, V transposed)
    gemm_bf16<0><<<dim3(3 * DIM / 64, SLEN / 128), 256, SMEM_GEMM>>>(
        Xh, Xl, W1h, W1l, qkv_b, nullptr);

    // 3) rel-pos bias tables (h and w fused in one launch)
    rel_kernel<<<dim3(GRD, NH, 2), 256, rel_sm>>>(rph, rpw);

    // 4) mma.sync flash attention with fused rel bias -> split AO
    attn_mma_kernel<<<dim3(SLEN / 128, NH), 256, SMEM_ATTN>>>();

    // 5) proj GEMM (tensor) -> out
    gemm_bf16<1><<<dim3(DIM / 64, SLEN / 128), 256, SMEM_GEMM>>>(
        AOh, AOl, W2h, W2l, proj_b, out);
}

// round 5
// speedup vs baseline: 3.1174x; 1.0164x over previous
#include <cuda_runtime.h>
#include <cuda_bf16.h>
#include <cstdint>

#define NH   12
#define SLEN 4096
#define HD   64
#define DIM  768
#define GRD  64

// ---------------- scratch ----------------------------------------------------
__device__ float g_relh[NH * SLEN * GRD];
__device__ float g_relw[NH * SLEN * GRD];

// split-bf16 operands (hi + lo ~ fp32)
__device__ __nv_bfloat16 g_Qh[NH * SLEN * HD];   // pre-scaled by 0.125
__device__ __nv_bfloat16 g_Ql[NH * SLEN * HD];
__device__ __nv_bfloat16 g_Kh[NH * SLEN * HD];
__device__ __nv_bfloat16 g_Kl[NH * SLEN * HD];
__device__ __nv_bfloat16 g_Vth[NH * HD * SLEN];  // transposed: [head][c][s]
__device__ __nv_bfloat16 g_Vtl[NH * HD * SLEN];

__device__ __nv_bfloat16 g_Xh[SLEN * DIM];       // x split
__device__ __nv_bfloat16 g_Xl[SLEN * DIM];
__device__ __nv_bfloat16 g_W1h[3 * DIM * DIM];   // qkv_w split
__device__ __nv_bfloat16 g_W1l[3 * DIM * DIM];
__device__ __nv_bfloat16 g_W2h[DIM * DIM];       // proj_w split
__device__ __nv_bfloat16 g_W2l[DIM * DIM];
__device__ __nv_bfloat16 g_aoh[SLEN * DIM];      // attention out split
__device__ __nv_bfloat16 g_aol[SLEN * DIM];

// ---------------- helpers -----------------------------------------------------
__device__ __forceinline__ uint32_t smem_u32(const void* p) {
    uint32_t a;
    asm("{ .reg .u64 t; cvta.to.shared.u64 t, %1; cvt.u32.u64 %0, t; }" : "=r"(a) : "l"(p));
    return a;
}

#define CP_ASYNC16(sm, gp) \
    asm volatile("cp.async.cg.shared.global [%0], [%1], 16;" :: "r"(sm), "l"(gp))
#define CP_COMMIT()  asm volatile("cp.async.commit_group;")
#define CP_WAIT1()   asm volatile("cp.async.wait_group 1;")
#define CP_WAIT0()   asm volatile("cp.async.wait_group 0;")

#define LDSM_X2(r0, r1, addr) \
    asm volatile("ldmatrix.sync.aligned.m8n8.x2.shared.b16 {%0,%1}, [%2];" \
                 : "=r"(r0), "=r"(r1) : "r"(addr))
#define LDSM_X4(r0, r1, r2, r3, addr) \
    asm volatile("ldmatrix.sync.aligned.m8n8.x4.shared.b16 {%0,%1,%2,%3}, [%4];" \
                 : "=r"(r0), "=r"(r1), "=r"(r2), "=r"(r3) : "r"(addr))

#define MMA16816(d, a, b0, b1) \
    asm volatile("mma.sync.aligned.m16n8k16.row.col.f32.bf16.bf16.f32 " \
        "{%0,%1,%2,%3}, {%4,%5,%6,%7}, {%8,%9}, {%0,%1,%2,%3};" \
        : "+f"((d)[0]), "+f"((d)[1]), "+f"((d)[2]), "+f"((d)[3]) \
        : "r"((a)[0]), "r"((a)[1]), "r"((a)[2]), "r"((a)[3]), "r"(b0), "r"(b1))

__device__ __forceinline__ void split2(float x, float y, uint32_t& hi, uint32_t& lo) {
    __nv_bfloat162 h = __float22bfloat162_rn(make_float2(x, y));
    float rx = x - __low2float(h);
    float ry = y - __high2float(h);
    __nv_bfloat162 l = __float22bfloat162_rn(make_float2(rx, ry));
    hi = *reinterpret_cast<uint32_t*>(&h);
    lo = *reinterpret_cast<uint32_t*>(&l);
}

// ---------------- input conversion (x, qkv_w, proj_w -> split bf16) ----------
#define NX (SLEN * DIM)
#define NW1 (3 * DIM * DIM)
#define NW2 (DIM * DIM)
__global__ void convert_in(const float* __restrict__ x,
                           const float* __restrict__ w1,
                           const float* __restrict__ w2)
{
    for (size_t i = (size_t)blockIdx.x * 256 + threadIdx.x;
         i < (size_t)(NX + NW1 + NW2); i += (size_t)gridDim.x * 256) {
        float v; __nv_bfloat16 *dh, *dl; size_t j;
        if (i < NX)            { j = i;             v = x[j];  dh = g_Xh;  dl = g_Xl;  }
        else if (i < NX + NW1) { j = i - NX;        v = w1[j]; dh = g_W1h; dl = g_W1l; }
        else                   { j = i - NX - NW1;  v = w2[j]; dh = g_W2h; dl = g_W2l; }
        __nv_bfloat16 h = __float2bfloat16(v);
        dh[j] = h;
        dl[j] = __float2bfloat16(v - __bfloat162float(h));
    }
}

// ---------------- split-bf16 tensor GEMM (proven round 4) --------------------
#define TG 80
#define G_AH 0
#define G_AL (128 * TG)
#define G_BH (2 * 128 * TG)
#define G_BL (2 * 128 * TG + 64 * TG)
#define G_STG (2 * 128 * TG + 2 * 64 * TG)
#define SMEM_GEMM (2 * G_STG)

template <int MODE>
__global__ void __launch_bounds__(256) gemm_bf16(
    const __nv_bfloat16* __restrict__ Agh, const __nv_bfloat16* __restrict__ Agl,
    const __nv_bfloat16* __restrict__ Bgh, const __nv_bfloat16* __restrict__ Bgl,
    const float* __restrict__ bias, float* __restrict__ out)
{
    extern __shared__ char smem[];
    const uint32_t sb = smem_u32(smem);
    const int tid  = threadIdx.x;
    const int lane = tid & 31;
    const int warp = tid >> 5;
    const int g    = lane >> 2;
    const int tm   = lane & 3;
    const int bm   = blockIdx.y * 128;
    const int bn   = blockIdx.x * 64;
    const int qr   = warp * 16;

    auto load_tile = [&](int buf, int kt) {
        const uint32_t st = sb + buf * G_STG;
        const int k0 = kt * 32;
#pragma unroll
        for (int rep = 0; rep < 6; rep++) {
            int c = tid + rep * 256;
            if (c < 512) {
                int row = c >> 2, off = c & 3;
                CP_ASYNC16(st + G_AH + row * TG + off * 16,
                           Agh + (size_t)(bm + row) * DIM + k0 + off * 8);
            } else if (c < 1024) {
                int cc = c - 512, row = cc >> 2, off = cc & 3;
                CP_ASYNC16(st + G_AL + row * TG + off * 16,
                           Agl + (size_t)(bm + row) * DIM + k0 + off * 8);
            } else if (c < 1280) {
                int cc = c - 1024, row = cc >> 2, off = cc & 3;
                CP_ASYNC16(st + G_BH + row * TG + off * 16,
                           Bgh + (size_t)(bn + row) * DIM + k0 + off * 8);
            } else {
                int cc = c - 1280, row = cc >> 2, off = cc & 3;
                CP_ASYNC16(st + G_BL + row * TG + off * 16,
                           Bgl + (size_t)(bn + row) * DIM + k0 + off * 8);
            }
        }
    };

    const uint32_t arow = (uint32_t)((lane & 15) * TG + (lane >> 4) * 16) + qr * TG;
    const uint32_t brow = (uint32_t)((lane & 7) * TG + (((lane & 15) >> 3) << 4));

    float sc[8][4];
#pragma unroll
    for (int nb = 0; nb < 8; nb++)
#pragma unroll
        for (int j = 0; j < 4; j++) sc[nb][j] = 0.0f;

    load_tile(0, 0);
    CP_COMMIT();

    for (int kt = 0; kt < 24; kt++) {
        if (kt < 23) { load_tile((kt + 1) & 1, kt + 1); CP_COMMIT(); CP_WAIT1(); }
        else         { CP_WAIT0(); }
        __syncthreads();

        const uint32_t st = sb + (kt & 1) * G_STG;
#pragma unroll
        for (int ks = 0; ks < 2; ks++) {
            uint32_t ah[4], al[4];
            LDSM_X4(ah[0], ah[1], ah[2], ah[3], st + G_AH + arow + ks * 32);
            LDSM_X4(al[0], al[1], al[2], al[3], st + G_AL + arow + ks * 32);
#pragma unroll
            for (int nb = 0; nb < 8; nb++) {
                uint32_t bh0, bh1, bl0, bl1;
                LDSM_X2(bh0, bh1, st + G_BH + brow + nb * (8 * TG) + ks * 32);
                LDSM_X2(bl0, bl1, st + G_BL + brow + nb * (8 * TG) + ks * 32);
                MMA16816(sc[nb], ah, bh0, bh1);
                MMA16816(sc[nb], ah, bl0, bl1);
                MMA16816(sc[nb], al, bh0, bh1);
            }
        }
        __syncthreads();
    }

    const int r0 = bm + qr + g, r1 = r0 + 8;
    if (MODE == 1) {
#pragma unroll
        for (int nb = 0; nb < 8; nb++) {
            const int jj = bn + nb * 8 + tm * 2;
            const float b0 = bias[jj], b1 = bias[jj + 1];
            *(float2*)&out[(size_t)r0 * DIM + jj] = make_float2(sc[nb][0] + b0, sc[nb][1] + b1);
            *(float2*)&out[(size_t)r1 * DIM + jj] = make_float2(sc[nb][2] + b0, sc[nb][3] + b1);
        }
    } else {
        const int which = bn / DIM;
        const int head  = (bn % DIM) >> 6;
#pragma unroll
        for (int nb = 0; nb < 8; nb++) {
            const int jj  = bn + nb * 8 + tm * 2;
            const int col = nb * 8 + tm * 2;
            const float b0 = bias[jj], b1 = bias[jj + 1];
            float v00 = sc[nb][0] + b0, v01 = sc[nb][1] + b1;
            float v10 = sc[nb][2] + b0, v11 = sc[nb][3] + b1;
            if (which == 0) {
                uint32_t h, l;
                split2(v00 * 0.125f, v01 * 0.125f, h, l);
                *(uint32_t*)&g_Qh[((size_t)head * SLEN + r0) * HD + col] = h;
                *(uint32_t*)&g_Ql[((size_t)head * SLEN + r0) * HD + col] = l;
                split2(v10 * 0.125f, v11 * 0.125f, h, l);
                *(uint32_t*)&g_Qh[((size_t)head * SLEN + r1) * HD + col] = h;
                *(uint32_t*)&g_Ql[((size_t)head * SLEN + r1) * HD + col] = l;
            } else if (which == 1) {
                uint32_t h, l;
                split2(v00, v01, h, l);
                *(uint32_t*)&g_Kh[((size_t)head * SLEN + r0) * HD + col] = h;
                *(uint32_t*)&g_Kl[((size_t)head * SLEN + r0) * HD + col] = l;
                split2(v10, v11, h, l);
                *(uint32_t*)&g_Kh[((size_t)head * SLEN + r1) * HD + col] = h;
                *(uint32_t*)&g_Kl[((size_t)head * SLEN + r1) * HD + col] = l;
            } else {
                float vv[4] = {v00, v01, v10, v11};
                int rr[4] = {r0, r0, r1, r1};
                int cc[4] = {col, col + 1, col, col + 1};
#pragma unroll
                for (int e = 0; e < 4; e++) {
                    __nv_bfloat16 h = __float2bfloat16(vv[e]);
                    size_t ti = ((size_t)head * HD + cc[e]) * SLEN + rr[e];
                    g_Vth[ti] = h;
                    g_Vtl[ti] = __float2bfloat16(vv[e] - __bfloat162float(h));
                }
            }
        }
    }
}

// ---------------- rel-pos bias (merged h/w; Q from split) --------------------
#define REL_SM_FLOATS (64 * 68 + 127 * 65)
__global__ void rel_kernel(const float* __restrict__ rph,
                           const float* __restrict__ rpw)
{
    extern __shared__ float sm[];
    float* Qs = sm;
    float* R  = sm + 64 * 68;
    const int qh = blockIdx.x, head = blockIdx.y;
    const int isW = blockIdx.z;
    const float* relpos = isW ? rpw : rph;
    const int tid = threadIdx.x;
    const int tx = tid & 15, ty = tid >> 4;

    const __nv_bfloat16* Qhg = &g_Qh[((size_t)head * SLEN + qh * GRD) * HD];
    const __nv_bfloat16* Qlg = &g_Ql[((size_t)head * SLEN + qh * GRD) * HD];
    for (int t = tid; t < 4096; t += 256) {
        int c = t & 63, qw = t >> 6;
        Qs[c * 68 + qw] = 8.0f * (__bfloat162float(Qhg[(size_t)qw * HD + c]) +
                                  __bfloat162float(Qlg[(size_t)qw * HD + c]));
    }

    if (!isW) {
        for (int t = tid; t < 4096; t += 256) {
            int c = t & 63, kh = t >> 6;
            R[c * 68 + kh] = relpos[(qh - kh + 63) * 64 + c];
        }
        __syncthreads();
        float acc[4][4] = {};
#pragma unroll 4
        for (int c = 0; c < 64; c++) {
            float4 a = *(const float4*)&Qs[c * 68 + (ty << 2)];
            float4 b = *(const float4*)&R[c * 68 + (tx << 2)];
            float av[4] = {a.x, a.y, a.z, a.w};
            float bv[4] = {b.x, b.y, b.z, b.w};
#pragma unroll
            for (int i = 0; i < 4; i++)
#pragma unroll
                for (int j = 0; j < 4; j++) acc[i][j] += av[i] * bv[j];
        }
#pragma unroll
        for (int i = 0; i < 4; i++)
#pragma unroll
            for (int j = 0; j < 4; j++) {
                int qw = (ty << 2) + i, kh = (tx << 2) + j;
                g_relh[((size_t)head * SLEN + qh * 64 + qw) * 64 + kh] = acc[i][j];
            }
    } else {
        for (int t = tid; t < 127 * 64; t += 256) {
            int c = t & 63, rr = t >> 6;
            R[rr * 65 + c] = relpos[rr * 64 + c];
        }
        __syncthreads();
        float acc[4][4] = {};
        const int qwb = ty << 2, kwb = tx << 2;
        for (int c = 0; c < 64; c++) {
            float4 a = *(const float4*)&Qs[c * 68 + qwb];
            float av[4] = {a.x, a.y, a.z, a.w};
#pragma unroll
            for (int i = 0; i < 4; i++)
#pragma unroll
                for (int j = 0; j < 4; j++)
                    acc[i][j] += av[i] * R[(qwb + i - kwb - j + 63) * 65 + c];
        }
#pragma unroll
        for (int i = 0; i < 4; i++)
#pragma unroll
            for (int j = 0; j < 4; j++) {
                int qw = qwb + i, kw = kwb + j;
                g_relw[((size_t)head * SLEN + qh * 64 + qw) * 64 + kw] = acc[i][j];
            }
    }
}

// ---------------- mma.sync flash attention (q-tile 64, 2 CTAs/SM) ------------
// 128 threads = 4 warps; 16 q-rows/warp; key-tile 64 = 1 key-grid row.
// ldmatrix.x4 loads two n8 B-blocks per instruction.
#define TROW     144
#define T_KH     0
#define T_KL     (64 * TROW)
#define T_VH     (2 * 64 * TROW)
#define T_VL     (3 * 64 * TROW)
#define STAGE_B  (4 * 64 * TROW)             // 36864
#define RH_OFF   (2 * STAGE_B)               // 73728
#define RW_OFF   (RH_OFF + 64 * 66 * 4)      // +16896
#define SMEM_ATTN (RW_OFF + 64 * 66 * 4)     // 107520

__global__ void __launch_bounds__(128, 2) attn_mma_kernel()
{
    extern __shared__ char smem[];
    const uint32_t sb = smem_u32(smem);
    const int tid  = threadIdx.x;
    const int lane = tid & 31;
    const int warp = tid >> 5;
    const int g    = lane >> 2;
    const int tm   = lane & 3;
    const int head = blockIdx.y;
    const int q0   = blockIdx.x * 64;
    const int qr   = warp * 16;

    float* rhS = (float*)(smem + RH_OFF);
    float* rwS = (float*)(smem + RW_OFF);

    for (int t = tid; t < 4096; t += 128) {
        int row = t >> 6, k = t & 63;
        rhS[row * 66 + k] = g_relh[((size_t)head * SLEN + q0 + row) * 64 + k];
        rwS[row * 66 + k] = g_relw[((size_t)head * SLEN + q0 + row) * 64 + k];
    }

    uint32_t qhf[4][4], qlf[4][4];
    {
        const uint32_t* q0h = (const uint32_t*)(g_Qh + ((size_t)head * SLEN + q0 + qr + g) * HD);
        const uint32_t* q1h = (const uint32_t*)(g_Qh + ((size_t)head * SLEN + q0 + qr + g + 8) * HD);
        const uint32_t* q0l = (const uint32_t*)(g_Ql + ((size_t)head * SLEN + q0 + qr + g) * HD);
        const uint32_t* q1l = (const uint32_t*)(g_Ql + ((size_t)head * SLEN + q0 + qr + g + 8) * HD);
#pragma unroll
        for (int ks = 0; ks < 4; ks++) {
            qhf[ks][0] = q0h[ks * 8 + tm];     qhf[ks][1] = q1h[ks * 8 + tm];
            qhf[ks][2] = q0h[ks * 8 + tm + 4]; qhf[ks][3] = q1h[ks * 8 + tm + 4];
            qlf[ks][0] = q0l[ks * 8 + tm];     qlf[ks][1] = q1l[ks * 8 + tm];
            qlf[ks][2] = q0l[ks * 8 + tm + 4]; qlf[ks][3] = q1l[ks * 8 + tm + 4];
        }
    }

    // x4 B-operand address: lanes 0-7 nb0/k0, 8-15 nb0/k8, 16-23 nb1/k0, 24-31 nb1/k8
    const uint32_t b4off = (uint32_t)((lane & 7) * TROW + ((lane >> 3) & 1) * 16 +
                                      ((lane >> 4) & 1) * (8 * TROW));

    float o[8][4];
#pragma unroll
    for (int cb = 0; cb < 8; cb++)
#pragma unroll
        for (int j = 0; j < 4; j++) o[cb][j] = 0.0f;
    float m0 = -1e30f, m1 = -1e30f, l0 = 0.0f, l1 = 0.0f;

    const char* KhG = (const char*)(g_Kh + (size_t)head * SLEN * HD);
    const char* KlG = (const char*)(g_Kl + (size_t)head * SLEN * HD);
    const char* VhG = (const char*)(g_Vth + (size_t)head * HD * SLEN);
    const char* VlG = (const char*)(g_Vtl + (size_t)head * HD * SLEN);

    auto load_tiles = [&](int buf, int kt) {
        const uint32_t st = sb + buf * STAGE_B;
#pragma unroll
        for (int rep = 0; rep < 4; rep++) {
            int c = tid + rep * 128;           // 512 chunks per sub-tile
            int row = c >> 3, off = c & 7;
            CP_ASYNC16(st + T_KH + row * TROW + off * 16,
                       KhG + (size_t)(kt * 64 + row) * 128 + off * 16);
            CP_ASYNC16(st + T_KL + row * TROW + off * 16,
                       KlG + (size_t)(kt * 64 + row) * 128 + off * 16);
            CP_ASYNC16(st + T_VH + row * TROW + off * 16,
                       VhG + (size_t)row * 8192 + (size_t)kt * 128 + off * 16);
            CP_ASYNC16(st + T_VL + row * TROW + off * 16,
                       VlG + (size_t)row * 8192 + (size_t)kt * 128 + off * 16);
        }
    };

    load_tiles(0, 0);
    CP_COMMIT();

    for (int kt = 0; kt < 64; kt++) {
        if (kt < 63) { load_tiles((kt + 1) & 1, kt + 1); CP_COMMIT(); CP_WAIT1(); }
        else         { CP_WAIT0(); }
        __syncthreads();

        const uint32_t st  = sb + (kt & 1) * STAGE_B;
        const uint32_t kh0 = st + T_KH + b4off;
        const uint32_t kl0 = st + T_KL + b4off;
        const uint32_t vh0 = st + T_VH + b4off;
        const uint32_t vl0 = st + T_VL + b4off;

        // ---- S = Qh Kh + Qh Kl + Ql Kh ----
        float sc[8][4];
#pragma unroll
        for (int nb = 0; nb < 8; nb++)
#pragma unroll
            for (int j = 0; j < 4; j++) sc[nb][j] = 0.0f;

#pragma unroll
        for (int ks = 0; ks < 4; ks++) {
#pragma unroll
            for (int nb2 = 0; nb2 < 4; nb2++) {
                uint32_t bh0, bh1, bh2, bh3, bl0, bl1, bl2, bl3;
                LDSM_X4(bh0, bh1, bh2, bh3, kh0 + nb2 * (16 * TROW) + ks * 32);
                LDSM_X4(bl0, bl1, bl2, bl3, kl0 + nb2 * (16 * TROW) + ks * 32);
                MMA16816(sc[2 * nb2], qhf[ks], bh0, bh1);
                MMA16816(sc[2 * nb2], qhf[ks], bl0, bl1);
                MMA16816(sc[2 * nb2], qlf[ks], bh0, bh1);
                MMA16816(sc[2 * nb2 + 1], qhf[ks], bh2, bh3);
                MMA16816(sc[2 * nb2 + 1], qhf[ks], bl2, bl3);
                MMA16816(sc[2 * nb2 + 1], qlf[ks], bh2, bh3);
            }
        }

        // ---- bias + online softmax ----
        const int r0 = qr + g, r1 = r0 + 8;
        const float rh0 = rhS[r0 * 66 + kt];
        const float rh1 = rhS[r1 * 66 + kt];
        float mt0 = -1e30f, mt1 = -1e30f;
#pragma unroll
        for (int nb = 0; nb < 8; nb++) {
            float2 w0 = *(const float2*)&rwS[r0 * 66 + nb * 8 + tm * 2];
            float2 w1 = *(const float2*)&rwS[r1 * 66 + nb * 8 + tm * 2];
            sc[nb][0] += rh0 + w0.x;  sc[nb][1] += rh0 + w0.y;
            sc[nb][2] += rh1 + w1.x;  sc[nb][3] += rh1 + w1.y;
            mt0 = fmaxf(mt0, fmaxf(sc[nb][0], sc[nb][1]));
            mt1 = fmaxf(mt1, fmaxf(sc[nb][2], sc[nb][3]));
        }
        mt0 = fmaxf(mt0, __shfl_xor_sync(0xffffffffu, mt0, 1));
        mt0 = fmaxf(mt0, __shfl_xor_sync(0xffffffffu, mt0, 2));
        mt1 = fmaxf(mt1, __shfl_xor_sync(0xffffffffu, mt1, 1));
        mt1 = fmaxf(mt1, __shfl_xor_sync(0xffffffffu, mt1, 2));

        const float mn0 = fmaxf(m0, mt0);
        const float mn1 = fmaxf(m1, mt1);
        const float a0 = __expf(m0 - mn0);
        const float a1 = __expf(m1 - mn1);
        m0 = mn0; m1 = mn1;

        float s0 = 0.0f, s1 = 0.0f;
#pragma unroll
        for (int nb = 0; nb < 8; nb++) {
            sc[nb][0] = __expf(sc[nb][0] - mn0);
            sc[nb][1] = __expf(sc[nb][1] - mn0);
            sc[nb][2] = __expf(sc[nb][2] - mn1);
            sc[nb][3] = __expf(sc[nb][3] - mn1);
            s0 += sc[nb][0] + sc[nb][1];
            s1 += sc[nb][2] + sc[nb][3];
        }
        s0 += __shfl_xor_sync(0xffffffffu, s0, 1);
        s0 += __shfl_xor_sync(0xffffffffu, s0, 2);
        s1 += __shfl_xor_sync(0xffffffffu, s1, 1);
        s1 += __shfl_xor_sync(0xffffffffu, s1, 2);
        l0 = l0 * a0 + s0;
        l1 = l1 * a1 + s1;

#pragma unroll
        for (int cb = 0; cb < 8; cb++) {
            o[cb][0] *= a0; o[cb][1] *= a0;
            o[cb][2] *= a1; o[cb][3] *= a1;
        }

        // ---- O += Ph Vh + Ph Vl + Pl Vh ----
#pragma unroll
        for (int kb = 0; kb < 4; kb++) {
            uint32_t ph[4], pl[4];
            split2(sc[2 * kb][0],     sc[2 * kb][1],     ph[0], pl[0]);
            split2(sc[2 * kb][2],     sc[2 * kb][3],     ph[1], pl[1]);
            split2(sc[2 * kb + 1][0], sc[2 * kb + 1][1], ph[2], pl[2]);
            split2(sc[2 * kb + 1][2], sc[2 * kb + 1][3], ph[3], pl[3]);
#pragma unroll
            for (int cb2 = 0; cb2 < 4; cb2++) {
                uint32_t bh0, bh1, bh2, bh3, bl0, bl1, bl2, bl3;
                LDSM_X4(bh0, bh1, bh2, bh3, vh0 + cb2 * (16 * TROW) + kb * 32);
                LDSM_X4(bl0, bl1, bl2, bl3, vl0 + cb2 * (16 * TROW) + kb * 32);
                MMA16816(o[2 * cb2], ph, bh0, bh1);
                MMA16816(o[2 * cb2], ph, bl0, bl1);
                MMA16816(o[2 * cb2], pl, bh0, bh1);
                MMA16816(o[2 * cb2 + 1], ph, bh2, bh3);
                MMA16816(o[2 * cb2 + 1], ph, bl2, bl3);
                MMA16816(o[2 * cb2 + 1], pl, bh2, bh3);
            }
        }
        __syncthreads();
    }

    // ---- normalize + write split-bf16 attention output ----
    const float i0 = 1.0f / l0;
    const float i1 = 1.0f / l1;
    const size_t o0 = (size_t)(q0 + qr + g) * DIM + head * HD;
    const size_t o1 = (size_t)(q0 + qr + g + 8) * DIM + head * HD;
#pragma unroll
    for (int cb = 0; cb < 8; cb++) {
        const int col = cb * 8 + tm * 2;
        uint32_t h, l;
        split2(o[cb][0] * i0, o[cb][1] * i0, h, l);
        *(uint32_t*)&g_aoh[o0 + col] = h;
        *(uint32_t*)&g_aol[o0 + col] = l;
        split2(o[cb][2] * i1, o[cb][3] * i1, h, l);
        *(uint32_t*)&g_aoh[o1 + col] = h;
        *(uint32_t*)&g_aol[o1 + col] = l;
    }
}

// ---------------- launch ------------------------------------------------------
extern "C" void kernel_launch(void* const* d_in, const int* in_sizes, int n_in,
                              void* d_out, int out_size)
{
    const float* x      = (const float*)d_in[0];
    const float* qkv_w  = (const float*)d_in[1];
    const float* qkv_b  = (const float*)d_in[2];
    const float* proj_w = (const float*)d_in[3];
    const float* proj_b = (const float*)d_in[4];
    const float* rph    = (const float*)d_in[5];
    const float* rpw    = (const float*)d_in[6];
    float* out = (float*)d_out;

    const int rel_sm = REL_SM_FLOATS * (int)sizeof(float);
    cudaFuncSetAttribute(rel_kernel, cudaFuncAttributeMaxDynamicSharedMemorySize, rel_sm);
    cudaFuncSetAttribute(attn_mma_kernel, cudaFuncAttributeMaxDynamicSharedMemorySize, SMEM_ATTN);
    cudaFuncSetAttribute(gemm_bf16<0>, cudaFuncAttributeMaxDynamicSharedMemorySize, SMEM_GEMM);
    cudaFuncSetAttribute(gemm_bf16<1>, cudaFuncAttributeMaxDynamicSharedMemorySize, SMEM_GEMM);

    __nv_bfloat16 *Xh, *Xl, *W1h, *W1l, *W2h, *W2l, *AOh, *AOl;
    cudaGetSymbolAddress((void**)&Xh,  g_Xh);
    cudaGetSymbolAddress((void**)&Xl,  g_Xl);
    cudaGetSymbolAddress((void**)&W1h, g_W1h);
    cudaGetSymbolAddress((void**)&W1l, g_W1l);
    cudaGetSymbolAddress((void**)&W2h, g_W2h);
    cudaGetSymbolAddress((void**)&W2l, g_W2l);
    cudaGetSymbolAddress((void**)&AOh, g_aoh);
    cudaGetSymbolAddress((void**)&AOl, g_aol);

    // 1) split inputs to bf16 hi/lo
    convert_in<<<2048, 256>>>(x, qkv_w, proj_w);

    // 2) qkv GEMM (tensor) -> split Q/K/V (Q pre-scaled, V transposed)
    gemm_bf16<0><<<dim3(3 * DIM / 64, SLEN / 128), 256, SMEM_GEMM>>>(
        Xh, Xl, W1h, W1l, qkv_b, nullptr);

    // 3) rel-pos bias tables (h and w fused in one launch)
    rel_kernel<<<dim3(GRD, NH, 2), 256, rel_sm>>>(rph, rpw);

    // 4) mma.sync flash attention, q-tile 64, 2 CTAs/SM
    attn_mma_kernel<<<dim3(SLEN / 64, NH), 128, SMEM_ATTN>>>();

    // 5) proj GEMM (tensor) -> out
    gemm_bf16<1><<<dim3(DIM / 64, SLEN / 128), 256, SMEM_GEMM>>>(
        AOh, AOl, W2h, W2l, proj_b, out);
}